// round 13
// baseline (speedup 1.0000x reference)
#include <cuda_runtime.h>
#include <cuda_bf16.h>
#include <math.h>

#define N_NODES 40000
#define N_EDGES 640000
#define D 128
#define NLAYERS 3
#define BN_EPS 1e-5
#define TC_BM 64
#define TC_BLOCKS ((N_NODES + TC_BM - 1) / TC_BM) /* 625 */
#define TC_THREADS 512
#define LDAB 272  /* padded row pitch in bytes: 136 bf16 */

typedef unsigned int uint;

__device__ __forceinline__ uint smem_to_u32(const void* p) {
    uint a;
    asm("{ .reg .u64 t; cvta.to.shared.u64 t, %1; cvt.u32.u64 %0, t; }"
        : "=r"(a) : "l"(p));
    return a;
}

#define LDSM_X4(r0, r1, r2, r3, addr) \
    asm volatile("ldmatrix.sync.aligned.m8n8.x4.shared.b16 {%0,%1,%2,%3}, [%4];" \
                 : "=r"(r0), "=r"(r1), "=r"(r2), "=r"(r3) : "r"(addr))
#define LDSM_X2(r0, r1, addr) \
    asm volatile("ldmatrix.sync.aligned.m8n8.x2.shared.b16 {%0,%1}, [%2];" \
                 : "=r"(r0), "=r"(r1) : "r"(addr))
#define MMA_BF16(d, a0, a1, a2, a3, b0, b1) \
    asm volatile("mma.sync.aligned.m16n8k16.row.col.f32.bf16.bf16.f32 " \
                 "{%0,%1,%2,%3}, {%4,%5,%6,%7}, {%8,%9}, {%0,%1,%2,%3};" \
                 : "+f"((d)[0]), "+f"((d)[1]), "+f"((d)[2]), "+f"((d)[3]) \
                 : "r"(a0), "r"(a1), "r"(a2), "r"(a3), "r"(b0), "r"(b1))

// split fp32 float4 -> bf16 hi/lo packed pairs
__device__ __forceinline__ void bsplit4(const float4& a, uint2& h, uint2& l) {
    __nv_bfloat16 hx = __float2bfloat16_rn(a.x);
    __nv_bfloat16 hy = __float2bfloat16_rn(a.y);
    __nv_bfloat16 hz = __float2bfloat16_rn(a.z);
    __nv_bfloat16 hw = __float2bfloat16_rn(a.w);
    __nv_bfloat16 lx = __float2bfloat16_rn(a.x - __bfloat162float(hx));
    __nv_bfloat16 ly = __float2bfloat16_rn(a.y - __bfloat162float(hy));
    __nv_bfloat16 lz = __float2bfloat16_rn(a.z - __bfloat162float(hz));
    __nv_bfloat16 lw = __float2bfloat16_rn(a.w - __bfloat162float(hw));
    h.x = (uint)__bfloat16_as_ushort(hx) | ((uint)__bfloat16_as_ushort(hy) << 16);
    h.y = (uint)__bfloat16_as_ushort(hz) | ((uint)__bfloat16_as_ushort(hw) << 16);
    l.x = (uint)__bfloat16_as_ushort(lx) | ((uint)__bfloat16_as_ushort(ly) << 16);
    l.y = (uint)__bfloat16_as_ushort(lz) | ((uint)__bfloat16_as_ushort(lw) << 16);
}

// GPRO transform: v = relu(ga*v + gc) elementwise
__device__ __forceinline__ void gpro4(float4& v, const float4& ga, const float4& gc) {
    v.x = fmaxf(fmaf(ga.x, v.x, gc.x), 0.f);
    v.y = fmaxf(fmaf(ga.y, v.y, gc.y), 0.f);
    v.z = fmaxf(fmaf(ga.z, v.z, gc.z), 0.f);
    v.w = fmaxf(fmaf(ga.w, v.w, gc.w), 0.f);
}

// ---------------- scratch ----------------
__device__ int   g_deg[N_NODES];
__device__ int   g_cur[N_NODES];
__device__ int   g_offs[N_NODES + 1];
__device__ int2  g_sedge[N_EDGES];   // packed {src, ew-as-int}

__device__ float g_bufB[(size_t)N_NODES * D];
__device__ float g_bufZ[(size_t)N_NODES * D];

__device__ __nv_bfloat16 g_wthi[6 * D * D];  // W^T hi, [mat][n][k] row-major
__device__ __nv_bfloat16 g_wtlo[6 * D * D];  // W^T lo

// column-major partials: [col][block] for coalesced finalize reads
__device__ float g_psum[D * TC_BLOCKS];
__device__ float g_psq [D * TC_BLOCKS];
__device__ float g_a[D];
__device__ float g_c[D];

// ---------------- CSR build ----------------
__global__ void k_zero_deg() {
    int i = blockIdx.x * blockDim.x + threadIdx.x;
    if (i < N_NODES) g_deg[i] = 0;
}

__global__ void k_hist(const int* __restrict__ dst) {
    int e = blockIdx.x * blockDim.x + threadIdx.x;
    if (e < N_EDGES) atomicAdd(&g_deg[dst[e]], 1);
}

__global__ void k_scan() {
    __shared__ int sh[1024];
    int t = threadIdx.x;
    const int CH = (N_NODES + 1023) / 1024;
    int base = t * CH;
    int s = 0;
    for (int i = 0; i < CH; i++) {
        int idx = base + i;
        if (idx < N_NODES) s += g_deg[idx];
    }
    sh[t] = s;
    __syncthreads();
    for (int off = 1; off < 1024; off <<= 1) {
        int v = 0;
        if (t >= off) v = sh[t - off];
        __syncthreads();
        sh[t] += v;
        __syncthreads();
    }
    int run = (t == 0) ? 0 : sh[t - 1];
    for (int i = 0; i < CH; i++) {
        int idx = base + i;
        if (idx < N_NODES) {
            g_offs[idx] = run;
            run += g_deg[idx];
            g_cur[idx] = 0;
        }
    }
    if (t == 1023) g_offs[N_NODES] = run;
}

__global__ void k_scatter(const int* __restrict__ src, const int* __restrict__ dst,
                          const float* __restrict__ ew) {
    int e = blockIdx.x * blockDim.x + threadIdx.x;
    if (e >= N_EDGES) return;
    int d = dst[e];
    int p = g_offs[d] + atomicAdd(&g_cur[d], 1);
    g_sedge[p] = make_int2(src[e], __float_as_int(ew[e]));
}

// ---------------- W convert: transpose + bf16 split ----------------
__global__ void k_wconv(const float* __restrict__ W1, const float* __restrict__ W2) {
    extern __shared__ float ts[];  // [128][129]
    int m = blockIdx.x;
    int l = m >> 1;
    const float* src = (m & 1) ? (W2 + (size_t)l * D * D) : (W1 + (size_t)l * D * D);
    const float4* s4 = (const float4*)src;
    for (int e = threadIdx.x; e < D * D / 4; e += 256) {
        int k = e >> 5, n4 = e & 31;
        float4 v = s4[e];
        float* row = ts + k * 129 + n4 * 4;
        row[0] = v.x; row[1] = v.y; row[2] = v.z; row[3] = v.w;
    }
    __syncthreads();
    __nv_bfloat16* oh = g_wthi + (size_t)m * D * D;
    __nv_bfloat16* ol = g_wtlo + (size_t)m * D * D;
    for (int idx = threadIdx.x; idx < D * D / 8; idx += 256) {
        int n = idx >> 4, kg = idx & 15;
        uint uh[4], ul[4];
#pragma unroll
        for (int p = 0; p < 4; p++) {
            float f0 = ts[(kg * 8 + p * 2    ) * 129 + n];
            float f1 = ts[(kg * 8 + p * 2 + 1) * 129 + n];
            __nv_bfloat16 h0 = __float2bfloat16_rn(f0);
            __nv_bfloat16 h1 = __float2bfloat16_rn(f1);
            __nv_bfloat16 l0 = __float2bfloat16_rn(f0 - __bfloat162float(h0));
            __nv_bfloat16 l1 = __float2bfloat16_rn(f1 - __bfloat162float(h1));
            uh[p] = (uint)__bfloat16_as_ushort(h0) | ((uint)__bfloat16_as_ushort(h1) << 16);
            ul[p] = (uint)__bfloat16_as_ushort(l0) | ((uint)__bfloat16_as_ushort(l1) << 16);
        }
        ((uint4*)oh)[idx] = make_uint4(uh[0], uh[1], uh[2], uh[3]);
        ((uint4*)ol)[idx] = make_uint4(ul[0], ul[1], ul[2], ul[3]);
    }
}

// ---------------- tensor-core fused GEMM (mma.sync bf16-split, BM=64, occ 2) ----------------
// CTA: 64 rows x 128 cols, 512 threads (16 warps = 4 m-tiles x 4 n-quarters).
// Gather: unroll-4, packed int2 edges, 4 feature loads in flight.
// acc = Ah*Bh + Al*Bh + Ah*Bl (fp32), K=128 via 8 k-tiles of 16.
// Stats: per-warp quarter ownership, fixed-order 4-warp sum (deterministic),
// written column-major for coalesced finalize.
template <bool GATHER, bool GPRO, bool PRO, bool RELUOUT>
__global__ void __launch_bounds__(TC_THREADS, 2)
k_gemm_tc(const float* __restrict__ X, int wmat, const float* __restrict__ bias,
          const float* __restrict__ epsl, int layer, float* __restrict__ Y) {
    extern __shared__ char smp[];
    __shared__ float bias_s[D];

    const uint A_HI = 0, A_LO = 17408, B_HI = 34816, B_LO = 69632;
    // reduction scratch overlays the A region after the mainloop
    float* red_s = (float*)smp;             // [16][128]
    float* red_q = (float*)(smp + 8192);    // [16][128]

    int tid  = threadIdx.x;
    int wid  = tid >> 5;
    int lane = tid & 31;
    int row0 = blockIdx.x * TC_BM;

    uint sbase = smem_to_u32(smp);

    if (tid < D) bias_s[tid] = bias[tid];

    // ---- stage B (pre-split W^T, [n][k] row-major -> padded rows) ----
    {
        const uint4* bh4 = ((const uint4*)g_wthi) + (size_t)wmat * 2048;
        const uint4* bl4 = ((const uint4*)g_wtlo) + (size_t)wmat * 2048;
        for (int idx = tid; idx < 2048; idx += TC_THREADS) {
            int n = idx >> 4, kg = idx & 15;
            uint o = (uint)(n * LDAB + kg * 16);
            *(uint4*)(smp + B_HI + o) = bh4[idx];
            *(uint4*)(smp + B_LO + o) = bl4[idx];
        }
    }

    // ---- stage A (gather or load+PRO), split to bf16 hi/lo ----
    if (GATHER) {
        const float4* h4 = (const float4*)X;
        float ep = 1.f + epsl[layer];
        float4 ga, gc;
        if (GPRO) {
            ga = *(const float4*)(g_a + lane * 4);
            gc = *(const float4*)(g_c + lane * 4);
        }
        for (int i = wid; i < TC_BM; i += 16) {
            int node = row0 + i;
            float4 a = make_float4(0.f, 0.f, 0.f, 0.f);
            if (node < N_NODES) {
                int beg = g_offs[node], end = g_offs[node + 1];
                int e = beg;
                for (; e + 3 < end; e += 4) {
                    int2 p0 = g_sedge[e];
                    int2 p1 = g_sedge[e + 1];
                    int2 p2 = g_sedge[e + 2];
                    int2 p3 = g_sedge[e + 3];
                    float4 v0 = h4[(size_t)p0.x * 32 + lane];
                    float4 v1 = h4[(size_t)p1.x * 32 + lane];
                    float4 v2 = h4[(size_t)p2.x * 32 + lane];
                    float4 v3 = h4[(size_t)p3.x * 32 + lane];
                    if (GPRO) {
                        gpro4(v0, ga, gc); gpro4(v1, ga, gc);
                        gpro4(v2, ga, gc); gpro4(v3, ga, gc);
                    }
                    float w0 = __int_as_float(p0.y), w1 = __int_as_float(p1.y);
                    float w2 = __int_as_float(p2.y), w3 = __int_as_float(p3.y);
                    a.x = fmaf(w0, v0.x, a.x); a.y = fmaf(w0, v0.y, a.y);
                    a.z = fmaf(w0, v0.z, a.z); a.w = fmaf(w0, v0.w, a.w);
                    a.x = fmaf(w1, v1.x, a.x); a.y = fmaf(w1, v1.y, a.y);
                    a.z = fmaf(w1, v1.z, a.z); a.w = fmaf(w1, v1.w, a.w);
                    a.x = fmaf(w2, v2.x, a.x); a.y = fmaf(w2, v2.y, a.y);
                    a.z = fmaf(w2, v2.z, a.z); a.w = fmaf(w2, v2.w, a.w);
                    a.x = fmaf(w3, v3.x, a.x); a.y = fmaf(w3, v3.y, a.y);
                    a.z = fmaf(w3, v3.z, a.z); a.w = fmaf(w3, v3.w, a.w);
                }
                for (; e < end; e++) {
                    int2 p0 = g_sedge[e];
                    float4 v0 = h4[(size_t)p0.x * 32 + lane];
                    if (GPRO) gpro4(v0, ga, gc);
                    float w0 = __int_as_float(p0.y);
                    a.x = fmaf(w0, v0.x, a.x); a.y = fmaf(w0, v0.y, a.y);
                    a.z = fmaf(w0, v0.z, a.z); a.w = fmaf(w0, v0.w, a.w);
                }
                float4 sf = h4[(size_t)node * 32 + lane];
                if (GPRO) gpro4(sf, ga, gc);
                a.x = fmaf(ep, sf.x, a.x); a.y = fmaf(ep, sf.y, a.y);
                a.z = fmaf(ep, sf.z, a.z); a.w = fmaf(ep, sf.w, a.w);
            }
            uint2 h2, l2;
            bsplit4(a, h2, l2);
            uint o = (uint)(i * LDAB + lane * 8);
            *(uint2*)(smp + A_HI + o) = h2;
            *(uint2*)(smp + A_LO + o) = l2;
        }
    } else {
        const float4* X4 = (const float4*)X;
        for (int i = wid; i < TC_BM; i += 16) {
            int node = row0 + i;
            float4 v = make_float4(0.f, 0.f, 0.f, 0.f);
            if (node < N_NODES) {
                v = X4[(size_t)node * 32 + lane];
                if (PRO) {
                    int k = lane * 4;
                    v.x = fmaxf(fmaf(g_a[k    ], v.x, g_c[k    ]), 0.f);
                    v.y = fmaxf(fmaf(g_a[k + 1], v.y, g_c[k + 1]), 0.f);
                    v.z = fmaxf(fmaf(g_a[k + 2], v.z, g_c[k + 2]), 0.f);
                    v.w = fmaxf(fmaf(g_a[k + 3], v.w, g_c[k + 3]), 0.f);
                }
            }
            uint2 h2, l2;
            bsplit4(v, h2, l2);
            uint o = (uint)(i * LDAB + lane * 8);
            *(uint2*)(smp + A_HI + o) = h2;
            *(uint2*)(smp + A_LO + o) = l2;
        }
    }
    __syncthreads();

    // ---- mma mainloop: warp = (m-tile mt rows mt*16.., n-quarter nq cols nq..nq+31) ----
    int mt = wid >> 2;
    int nq = (wid & 3) * 32;
    float acc[4][4];
#pragma unroll
    for (int j = 0; j < 4; j++)
#pragma unroll
        for (int c = 0; c < 4; c++) acc[j][c] = 0.f;

    uint aRowOff = (uint)((mt * 16 + (lane & 15)) * LDAB + ((lane >> 4) << 4));
    uint aHiAddr = sbase + A_HI + aRowOff;
    uint aLoAddr = sbase + A_LO + aRowOff;
    uint bRowOff = (uint)((nq + (lane & 7)) * LDAB + (((lane >> 3) & 1) << 4));
    uint bHiAddr = sbase + B_HI + bRowOff;
    uint bLoAddr = sbase + B_LO + bRowOff;

#pragma unroll
    for (int kt = 0; kt < 8; kt++) {
        uint ah0, ah1, ah2, ah3, al0, al1, al2, al3;
        LDSM_X4(ah0, ah1, ah2, ah3, aHiAddr + kt * 32);
        LDSM_X4(al0, al1, al2, al3, aLoAddr + kt * 32);
#pragma unroll
        for (int j = 0; j < 4; j++) {
            uint bh0, bh1, bl0, bl1;
            uint bo = (uint)(j * 8 * LDAB + kt * 32);
            LDSM_X2(bh0, bh1, bHiAddr + bo);
            LDSM_X2(bl0, bl1, bLoAddr + bo);
            MMA_BF16(acc[j], ah0, ah1, ah2, ah3, bh0, bh1);
            MMA_BF16(acc[j], al0, al1, al2, al3, bh0, bh1);
            MMA_BF16(acc[j], ah0, ah1, ah2, ah3, bl0, bl1);
        }
    }
    __syncthreads();  // all warps done reading A region -> safe to reuse for stats

    // ---- epilogue: bias/relu, store, column stats ----
    int r0 = row0 + mt * 16 + (lane >> 2);
    int r1 = r0 + 8;
    bool v0 = r0 < N_NODES, v1 = r1 < N_NODES;
    float s[8], q[8];
#pragma unroll
    for (int j = 0; j < 4; j++) {
        int c = nq + j * 8 + (lane & 3) * 2;
        float o0 = acc[j][0] + bias_s[c];
        float o1 = acc[j][1] + bias_s[c + 1];
        float o2 = acc[j][2] + bias_s[c];
        float o3 = acc[j][3] + bias_s[c + 1];
        if (RELUOUT) {
            o0 = fmaxf(o0, 0.f); o1 = fmaxf(o1, 0.f);
            o2 = fmaxf(o2, 0.f); o3 = fmaxf(o3, 0.f);
        }
        if (!v0) { o0 = 0.f; o1 = 0.f; }
        if (!v1) { o2 = 0.f; o3 = 0.f; }
        if (v0) *(float2*)(Y + (size_t)r0 * D + c) = make_float2(o0, o1);
        if (v1) *(float2*)(Y + (size_t)r1 * D + c) = make_float2(o2, o3);
        s[j * 2    ] = o0 + o2;
        s[j * 2 + 1] = o1 + o3;
        q[j * 2    ] = fmaf(o0, o0, o2 * o2);
        q[j * 2 + 1] = fmaf(o1, o1, o3 * o3);
    }
    // butterfly over the 8 row-groups (lane bits 2..4)
#pragma unroll
    for (int off = 4; off <= 16; off <<= 1) {
#pragma unroll
        for (int i = 0; i < 8; i++) {
            s[i] += __shfl_xor_sync(0xFFFFFFFF, s[i], off);
            q[i] += __shfl_xor_sync(0xFFFFFFFF, q[i], off);
        }
    }
    if (lane < 4) {
#pragma unroll
        for (int j = 0; j < 4; j++) {
            int c = nq + j * 8 + lane * 2;
            red_s[wid * D + c    ] = s[j * 2    ];
            red_s[wid * D + c + 1] = s[j * 2 + 1];
            red_q[wid * D + c    ] = q[j * 2    ];
            red_q[wid * D + c + 1] = q[j * 2 + 1];
        }
    }
    __syncthreads();
    if (tid < D) {
        // column tid is owned by warps w = 4*mt + (tid>>5); sum ONLY those 4
        int qsel = tid >> 5;
        float ps = 0.f, pq = 0.f;
#pragma unroll
        for (int m2 = 0; m2 < 4; m2++) {
            int w = m2 * 4 + qsel;
            ps += red_s[w * D + tid];
            pq += red_q[w * D + tid];
        }
        // column-major partials for coalesced finalize reads
        g_psum[tid * TC_BLOCKS + blockIdx.x] = ps;
        g_psq [tid * TC_BLOCKS + blockIdx.x] = pq;
    }
}

// ---------------- BN finalize: one block per feature column (coalesced reads) ----------------
__global__ void k_finalize(const float* __restrict__ gamma,
                           const float* __restrict__ beta) {
    __shared__ double sh[2][256];
    int c = blockIdx.x;
    int t = threadIdx.x;
    const float* ps = g_psum + (size_t)c * TC_BLOCKS;
    const float* pq = g_psq  + (size_t)c * TC_BLOCKS;
    double s = 0.0, q = 0.0;
    for (int b = t; b < TC_BLOCKS; b += 256) {
        s += (double)ps[b];
        q += (double)pq[b];
    }
    sh[0][t] = s; sh[1][t] = q;
    __syncthreads();
    for (int o = 128; o > 0; o >>= 1) {
        if (t < o) { sh[0][t] += sh[0][t + o]; sh[1][t] += sh[1][t + o]; }
        __syncthreads();
    }
    if (t == 0) {
        double m   = sh[0][0] / (double)N_NODES;
        double var = sh[1][0] / (double)N_NODES - m * m;
        if (var < 0.0) var = 0.0;
        float inv = (float)(1.0 / sqrt(var + (double)BN_EPS));
        float a = gamma[c] * inv;
        g_a[c] = a;
        g_c[c] = beta[c] - a * (float)m;
    }
}

// ---------------- BN2 + ReLU elementwise (final output) ----------------
__global__ void k_bn_relu(const float* __restrict__ Z, float* __restrict__ O) {
    int i = blockIdx.x * blockDim.x + threadIdx.x;
    const int total = N_NODES * D / 4;
    if (i >= total) return;
    float4 v = ((const float4*)Z)[i];
    int k = (i & 31) * 4;
    float4 o;
    o.x = fmaxf(fmaf(g_a[k    ], v.x, g_c[k    ]), 0.f);
    o.y = fmaxf(fmaf(g_a[k + 1], v.y, g_c[k + 1]), 0.f);
    o.z = fmaxf(fmaf(g_a[k + 2], v.z, g_c[k + 2]), 0.f);
    o.w = fmaxf(fmaf(g_a[k + 3], v.w, g_c[k + 3]), 0.f);
    ((float4*)O)[i] = o;
}

// ---------------- launch ----------------
extern "C" void kernel_launch(void* const* d_in, const int* in_sizes, int n_in,
                              void* d_out, int out_size) {
    const float* h    = (const float*)d_in[0];
    const int*   src  = (const int*)d_in[1];
    const int*   dst  = (const int*)d_in[2];
    const float* ew   = (const float*)d_in[3];
    const float* epsl = (const float*)d_in[4];
    const float* W1   = (const float*)d_in[5];
    const float* b1   = (const float*)d_in[6];
    const float* g1   = (const float*)d_in[7];
    const float* bt1  = (const float*)d_in[8];
    const float* W2   = (const float*)d_in[9];
    const float* b2   = (const float*)d_in[10];
    const float* g2   = (const float*)d_in[11];
    const float* bt2  = (const float*)d_in[12];
    float* out = (float*)d_out;

    const int tc_smem = 104448;  // A_hi 17408 + A_lo 17408 + B_hi 34816 + B_lo 34816
    cudaFuncSetAttribute(k_gemm_tc<true, false, false, false>,
                         cudaFuncAttributeMaxDynamicSharedMemorySize, tc_smem);
    cudaFuncSetAttribute(k_gemm_tc<true, true, false, false>,
                         cudaFuncAttributeMaxDynamicSharedMemorySize, tc_smem);
    cudaFuncSetAttribute(k_gemm_tc<false, false, true, true>,
                         cudaFuncAttributeMaxDynamicSharedMemorySize, tc_smem);
    const int wc_smem = 128 * 129 * 4;
    cudaFuncSetAttribute(k_wconv,
                         cudaFuncAttributeMaxDynamicSharedMemorySize, wc_smem);

    void *pB = nullptr, *pZ = nullptr;
    cudaGetSymbolAddress(&pB, g_bufB);
    cudaGetSymbolAddress(&pZ, g_bufZ);
    float* bufB = (float*)pB;
    float* bufZ = (float*)pZ;

    // CSR build + W transpose/split (per replay; deterministic)
    k_zero_deg<<<(N_NODES + 255) / 256, 256>>>();
    k_hist<<<(N_EDGES + 255) / 256, 256>>>(dst);
    k_scan<<<1, 1024>>>();
    k_scatter<<<(N_EDGES + 255) / 256, 256>>>(src, dst, ew);
    k_wconv<<<6, 256, wc_smem>>>(W1, W2);

    for (int l = 0; l < NLAYERS; l++) {
        // y = ((1+eps)*T(h) + sum ew*T(h[src])) @ W1 + b1   (+BN1 stats)
        if (l == 0)
            k_gemm_tc<true, false, false, false><<<TC_BLOCKS, TC_THREADS, tc_smem>>>(
                h, 0, b1, epsl, 0, bufB);
        else
            k_gemm_tc<true, true, false, false><<<TC_BLOCKS, TC_THREADS, tc_smem>>>(
                bufZ, l * 2, b1 + l * D, epsl, l, bufB);
        k_finalize<<<D, 256>>>(g1 + l * D, bt1 + l * D);
        // z2 = relu( relu(bn1(y)) @ W2 + b2 )   (+BN2 stats)
        k_gemm_tc<false, false, true, true><<<TC_BLOCKS, TC_THREADS, tc_smem>>>(
            bufB, l * 2 + 1, b2 + l * D, epsl, l, bufZ);
        k_finalize<<<D, 256>>>(g2 + l * D, bt2 + l * D);
    }
    // final h = relu(bn2(z2)) -> out
    k_bn_relu<<<N_NODES * D / 4 / 256, 256>>>(bufZ, out);
}